// round 3
// baseline (speedup 1.0000x reference)
#include <cuda_runtime.h>

// SNN: B=4096, T=256, I=7, H=64, O=8
// Layout: warp = 2 batches x 16 lanes; each lane owns 4 hidden units.
// Packed f32x2 math; spike carried as next reset; W2 pre-negated so
// spikes are stored as {0,-1} and reset-subtract becomes add.

#define THRESH 1.0f

typedef unsigned long long u64;

constexpr int T_ = 256;
constexpr int I_ = 7;
constexpr int H_ = 64;
constexpr int O_ = 8;
constexpr int WARPS_PER_BLOCK = 4;
constexpr int TCHUNK = 32;

__device__ __forceinline__ u64 pack2(float lo, float hi) {
    u64 r; asm("mov.b64 %0, {%1, %2};" : "=l"(r) : "f"(lo), "f"(hi)); return r;
}
__device__ __forceinline__ void unpack2(u64 v, float& lo, float& hi) {
    asm("mov.b64 {%0, %1}, %2;" : "=f"(lo), "=f"(hi) : "l"(v));
}
__device__ __forceinline__ u64 fma2(u64 a, u64 b, u64 c) {
    u64 d; asm("fma.rn.f32x2 %0, %1, %2, %3;" : "=l"(d) : "l"(a), "l"(b), "l"(c)); return d;
}
__device__ __forceinline__ u64 mul2(u64 a, u64 b) {
    u64 d; asm("mul.rn.f32x2 %0, %1, %2;" : "=l"(d) : "l"(a), "l"(b)); return d;
}
__device__ __forceinline__ u64 add2(u64 a, u64 b) {
    u64 d; asm("add.rn.f32x2 %0, %1, %2;" : "=l"(d) : "l"(a), "l"(b)); return d;
}

__global__ __launch_bounds__(WARPS_PER_BLOCK * 32)
void snn_kernel(const float* __restrict__ x,
                const float* __restrict__ hs,
                const float* __restrict__ W1,
                const float* __restrict__ b1,
                const float* __restrict__ W2,
                const float* __restrict__ b2,
                float* __restrict__ out,     // (B,T,8)
                float* __restrict__ newh,    // (B,T,64)
                int B)
{
    // x staged duplicated: each float stored twice so LDS.64 feeds FFMA2
    // directly. Pad per-batch region by 1 u64 to offset banks between the
    // two 16-lane groups.
    __shared__ u64 xs[WARPS_PER_BLOCK][2][TCHUNK * I_ + 1];

    const int w    = threadIdx.x >> 5;
    const int lane = threadIdx.x & 31;
    const int sub  = lane & 15;     // lane within batch group
    const int bsel = lane >> 4;     // which batch of the pair
    const int gw   = blockIdx.x * WARPS_PER_BLOCK + w;

    int b = gw * 2 + bsel;
    if (b >= B) b = B - 1;          // safe duplicate work (B is even here)

    const int h0 = 4 * sub;

    // Per-lane weights, packed
    u64 w1p[I_][2], w2n[O_][2], b1p[2];
#pragma unroll
    for (int i = 0; i < I_; i++) {
        w1p[i][0] = pack2(W1[(h0 + 0) * I_ + i], W1[(h0 + 1) * I_ + i]);
        w1p[i][1] = pack2(W1[(h0 + 2) * I_ + i], W1[(h0 + 3) * I_ + i]);
    }
    b1p[0] = pack2(b1[h0 + 0], b1[h0 + 1]);
    b1p[1] = pack2(b1[h0 + 2], b1[h0 + 3]);
#pragma unroll
    for (int o = 0; o < O_; o++) {
        w2n[o][0] = pack2(-W2[o * H_ + h0 + 0], -W2[o * H_ + h0 + 1]);
        w2n[o][1] = pack2(-W2[o * H_ + h0 + 2], -W2[o * H_ + h0 + 3]);
    }
    const float bias2 = b2[lane & 7];
    const u64 beta2 = pack2(0.8f, 0.8f);

    // Initial membrane + initial reset (= spike of initial mem)
    const float4 m4 = *reinterpret_cast<const float4*>(hs + (size_t)b * H_ + h0);
    u64 mem01 = pack2(m4.x, m4.y);
    u64 mem23 = pack2(m4.z, m4.w);
    u64 sn01  = pack2(m4.x > THRESH ? -1.0f : 0.0f, m4.y > THRESH ? -1.0f : 0.0f);
    u64 sn23  = pack2(m4.z > THRESH ? -1.0f : 0.0f, m4.w > THRESH ? -1.0f : 0.0f);

    const float* xb = x    + (size_t)b * T_ * I_;
    float*       nh = newh + (size_t)b * T_ * H_ + h0;
    float*       ob = out  + (size_t)b * T_ * O_;

    for (int c0 = 0; c0 < T_; c0 += TCHUNK) {
        // Stage this batch's x chunk into shared, duplicated.
        {
            const float* src = xb + c0 * I_;
            u64* dst = xs[w][bsel];
#pragma unroll
            for (int k = 0; k < (TCHUNK * I_) / 16; k++) {   // 14 iters
                const int idx = sub + k * 16;
                const float v = src[idx];
                dst[idx] = pack2(v, v);
            }
        }
        __syncwarp();

#pragma unroll 2
        for (int tt = 0; tt < TCHUNK; tt++) {
            const int t = c0 + tt;
            const u64* xr = &xs[w][bsel][tt * I_];

            // cur1 = x @ W1^T + b1 (4 hidden units, packed pairs)
            u64 c01 = b1p[0], c23 = b1p[1];
#pragma unroll
            for (int i = 0; i < I_; i++) {
                const u64 xv = xr[i];
                c01 = fma2(xv, w1p[i][0], c01);
                c23 = fma2(xv, w1p[i][1], c23);
            }

            // mem = beta*mem + cur - reset   (sn is -reset)
            mem01 = fma2(beta2, mem01, add2(c01, sn01));
            mem23 = fma2(beta2, mem23, add2(c23, sn23));

            // record post-update membranes: one STG.128, coalesced
            {
                ulonglong2 st; st.x = mem01; st.y = mem23;
                *reinterpret_cast<ulonglong2*>(nh + (size_t)t * H_) = st;
            }

            // spikes (stored negated; also next step's reset)
            float m0, m1, m2, m3;
            unpack2(mem01, m0, m1);
            unpack2(mem23, m2, m3);
            sn01 = pack2(m0 > THRESH ? -1.0f : 0.0f, m1 > THRESH ? -1.0f : 0.0f);
            sn23 = pack2(m2 > THRESH ? -1.0f : 0.0f, m3 > THRESH ? -1.0f : 0.0f);

            // per-lane output partials: p[o] = sum_h spk_h * W2[o,h]
            //   = sn01 . w2n[o][0] + sn23 . w2n[o][1]   (both negated)
            float p[O_];
#pragma unroll
            for (int o = 0; o < O_; o++) {
                const u64 acc = fma2(sn23, w2n[o][1], mul2(sn01, w2n[o][0]));
                float a, c; unpack2(acc, a, c);
                p[o] = a + c;
            }

            // Fold 8 values over the 16-lane group (serves 2 batches/warp).
            {
                const bool hi = (lane & 4) != 0;
                float t0 = __shfl_xor_sync(0xFFFFFFFFu, hi ? p[0] : p[4], 4);
                float t1 = __shfl_xor_sync(0xFFFFFFFFu, hi ? p[1] : p[5], 4);
                float t2 = __shfl_xor_sync(0xFFFFFFFFu, hi ? p[2] : p[6], 4);
                float t3 = __shfl_xor_sync(0xFFFFFFFFu, hi ? p[3] : p[7], 4);
                p[0] = (hi ? p[4] : p[0]) + t0;
                p[1] = (hi ? p[5] : p[1]) + t1;
                p[2] = (hi ? p[6] : p[2]) + t2;
                p[3] = (hi ? p[7] : p[3]) + t3;
            }
            {
                const bool hi = (lane & 2) != 0;
                float t0 = __shfl_xor_sync(0xFFFFFFFFu, hi ? p[0] : p[2], 2);
                float t1 = __shfl_xor_sync(0xFFFFFFFFu, hi ? p[1] : p[3], 2);
                p[0] = (hi ? p[2] : p[0]) + t0;
                p[1] = (hi ? p[3] : p[1]) + t1;
            }
            {
                const bool hi = (lane & 1) != 0;
                float t0 = __shfl_xor_sync(0xFFFFFFFFu, hi ? p[0] : p[1], 1);
                p[0] = (hi ? p[1] : p[0]) + t0;
            }
            p[0] += __shfl_xor_sync(0xFFFFFFFFu, p[0], 8);

            // lane holds out[o = lane&7], replicated at lane and lane+8
            if ((lane & 8) == 0)
                ob[t * O_ + (lane & 7)] = p[0] + bias2;
        }
        __syncwarp();
    }
}

extern "C" void kernel_launch(void* const* d_in, const int* in_sizes, int n_in,
                              void* d_out, int out_size)
{
    const float* x  = (const float*)d_in[0];
    const float* hs = (const float*)d_in[1];
    const float* W1 = (const float*)d_in[2];
    const float* b1 = (const float*)d_in[3];
    const float* W2 = (const float*)d_in[4];
    const float* b2 = (const float*)d_in[5];

    const int B = in_sizes[1] / H_;

    float* out  = (float*)d_out;                       // (B,T,O)
    float* newh = (float*)d_out + (size_t)B * T_ * O_; // (B,T,H)

    const int warps  = (B + 1) / 2;
    const int blocks = (warps + WARPS_PER_BLOCK - 1) / WARPS_PER_BLOCK;
    snn_kernel<<<blocks, WARPS_PER_BLOCK * 32>>>(x, hs, W1, b1, W2, b2,
                                                 out, newh, B);
}

// round 5
// speedup vs baseline: 1.6289x; 1.6289x over previous
#include <cuda_runtime.h>
#include <cuda_fp16.h>

// SNN: B=4096, T=256, I=7, H=64, O=8
// 1 batch/warp, 2 hidden units/lane. Recurrence in fp32 (f32x2 packed),
// output matvec deferred per 32-step chunk and done with HMMA m16n8k16
// (spikes exact in fp16; W2 split hi+lo fp16 for full precision).

#define THRESH 1.0f
#define BETA 0.8f

typedef unsigned long long u64;
typedef unsigned int u32;

constexpr int T_ = 256;
constexpr int I_ = 7;
constexpr int H_ = 64;
constexpr int O_ = 8;
constexpr int WPB = 4;
constexpr int TCHUNK = 32;
constexpr int SPK_STRIDE = 72;   // halves per row (64 + 8 pad) -> 144B rows

__device__ __forceinline__ u64 pack2(float lo, float hi) {
    u64 r; asm("mov.b64 %0, {%1, %2};" : "=l"(r) : "f"(lo), "f"(hi)); return r;
}
__device__ __forceinline__ void unpack2(u64 v, float& lo, float& hi) {
    asm("mov.b64 {%0, %1}, %2;" : "=f"(lo), "=f"(hi) : "l"(v));
}
__device__ __forceinline__ u64 fma2(u64 a, u64 b, u64 c) {
    u64 d; asm("fma.rn.f32x2 %0, %1, %2, %3;" : "=l"(d) : "l"(a), "l"(b), "l"(c)); return d;
}
// pack two f32 -> f16x2 (lo goes to low half)
__device__ __forceinline__ u32 cvt_f16x2(float lo, float hi) {
    u32 r; asm("cvt.rn.f16x2.f32 %0, %1, %2;" : "=r"(r) : "f"(hi), "f"(lo)); return r;
}
__device__ __forceinline__ void ldsm_x4(u32& r0, u32& r1, u32& r2, u32& r3, u32 addr) {
    asm volatile("ldmatrix.sync.aligned.m8n8.x4.shared.b16 {%0,%1,%2,%3}, [%4];"
                 : "=r"(r0), "=r"(r1), "=r"(r2), "=r"(r3) : "r"(addr));
}
__device__ __forceinline__ void mma16816(float& c0, float& c1, float& c2, float& c3,
                                         u32 a0, u32 a1, u32 a2, u32 a3,
                                         u32 b0, u32 b1) {
    asm volatile("mma.sync.aligned.m16n8k16.row.col.f32.f16.f16.f32 "
                 "{%0,%1,%2,%3},{%4,%5,%6,%7},{%8,%9},{%0,%1,%2,%3};"
                 : "+f"(c0), "+f"(c1), "+f"(c2), "+f"(c3)
                 : "r"(a0), "r"(a1), "r"(a2), "r"(a3), "r"(b0), "r"(b1));
}

__global__ __launch_bounds__(WPB * 32)
void snn_kernel(const float* __restrict__ x,
                const float* __restrict__ hs,
                const float* __restrict__ W1,
                const float* __restrict__ b1,
                const float* __restrict__ W2,
                const float* __restrict__ b2,
                float* __restrict__ out,     // (B,T,8)
                float* __restrict__ newh,    // (B,T,64)
                int B)
{
    // x duplicated per float into u64 so LDS.64 broadcast feeds FFMA2.
    __shared__ u64 xs[WPB][TCHUNK * I_];                    // 4*224*8 = 7 KB
    __shared__ __align__(16) unsigned short spk[WPB][TCHUNK][SPK_STRIDE]; // 18 KB

    const int w    = threadIdx.x >> 5;
    const int lane = threadIdx.x & 31;
    const int b    = blockIdx.x * WPB + w;
    if (b >= B) return;

    const int h0 = 2 * lane;

    // --- W1 rows packed for this lane's two hidden units ---
    u64 w1p[I_];
#pragma unroll
    for (int i = 0; i < I_; i++)
        w1p[i] = pack2(W1[h0 * I_ + i], W1[(h0 + 1) * I_ + i]);
    const u64 b1p = pack2(b1[h0], b1[h0 + 1]);

    // --- B fragments for HMMA (n8k16, col-major):
    // lane l -> o = l>>2, k pairs (l&3)*2 (+1), and +8.  Hi/lo fp16 split.
    u32 bhi[4][2], blo[4][2];
    {
        const int o  = lane >> 2;
        const int kp = (lane & 3) * 2;
#pragma unroll
        for (int kt = 0; kt < 4; kt++) {
#pragma unroll
            for (int half = 0; half < 2; half++) {
                const int k = kt * 16 + half * 8 + kp;
                float wa = W2[o * H_ + k], wb = W2[o * H_ + k + 1];
                __half ha = __float2half_rn(wa);
                __half hb = __float2half_rn(wb);
                __half la = __float2half_rn(wa - __half2float(ha));
                __half lb = __float2half_rn(wb - __half2float(hb));
                __half2 vh = __halves2half2(ha, hb);
                __half2 vl = __halves2half2(la, lb);
                bhi[kt][half] = *reinterpret_cast<u32*>(&vh);
                blo[kt][half] = *reinterpret_cast<u32*>(&vl);
            }
        }
    }
    // C-fragment bias: lane l holds cols 2*(l&3), 2*(l&3)+1
    const float bi0 = b2[2 * (lane & 3)];
    const float bi1 = b2[2 * (lane & 3) + 1];

    // --- initial membrane + initial reset ---
    const float2 m2 = *reinterpret_cast<const float2*>(hs + (size_t)b * H_ + h0);
    float mem0 = m2.x, mem1 = m2.y;
    float s0 = (mem0 > THRESH) ? 1.0f : 0.0f;
    float s1 = (mem1 > THRESH) ? 1.0f : 0.0f;

    const float* xb = x    + (size_t)b * T_ * I_;
    float*       nh = newh + (size_t)b * T_ * H_ + h0;
    float*       ob = out  + (size_t)b * T_ * O_;

    // ldmatrix per-lane row address inside this warp's spike tile
    const u32 spk_base = (u32)__cvta_generic_to_shared(&spk[w][0][0]);
    const u32 lm_addr0 = spk_base + (u32)(lane & 15) * (SPK_STRIDE * 2)
                                  + (u32)(lane >> 4) * 16;

    for (int c0 = 0; c0 < T_; c0 += TCHUNK) {
        // ---- stage x chunk (224 floats = 56 float4), duplicated ----
        {
            const float4* src = (const float4*)(xb + c0 * I_);
            u64* dst = xs[w];
#pragma unroll
            for (int k = 0; k < 2; k++) {
                const int idx = lane + k * 32;
                if (idx < TCHUNK * I_ / 4) {
                    const float4 v = __ldcs(&src[idx]);
                    ulonglong2 lo, hi;
                    lo.x = pack2(v.x, v.x); lo.y = pack2(v.y, v.y);
                    hi.x = pack2(v.z, v.z); hi.y = pack2(v.w, v.w);
                    *reinterpret_cast<ulonglong2*>(&dst[4 * idx])     = lo;
                    *reinterpret_cast<ulonglong2*>(&dst[4 * idx + 2]) = hi;
                }
            }
        }
        __syncwarp();

        // ---- phase 1: recurrence over 32 steps ----
#pragma unroll 4
        for (int tt = 0; tt < TCHUNK; tt++) {
            const int t = c0 + tt;
            const u64* xr = &xs[w][tt * I_];

            u64 c = b1p;
#pragma unroll
            for (int i = 0; i < I_; i++)
                c = fma2(xr[i], w1p[i], c);
            float c0f, c1f; unpack2(c, c0f, c1f);

            mem0 = fmaf(BETA, mem0, c0f - s0);
            mem1 = fmaf(BETA, mem1, c1f - s1);

            __stcs(reinterpret_cast<float2*>(nh + (size_t)t * H_),
                   make_float2(mem0, mem1));

            s0 = (mem0 > THRESH) ? 1.0f : 0.0f;
            s1 = (mem1 > THRESH) ? 1.0f : 0.0f;

            *reinterpret_cast<u32*>(&spk[w][tt][2 * lane]) = cvt_f16x2(s0, s1);
        }
        __syncwarp();

        // ---- phase 2: outputs for 32 steps via HMMA ----
#pragma unroll
        for (int mt = 0; mt < 2; mt++) {
            float d0 = bi0, d1 = bi1, d2 = bi0, d3 = bi1;
#pragma unroll
            for (int kt = 0; kt < 4; kt++) {
                u32 a0, a1, a2, a3;
                ldsm_x4(a0, a1, a2, a3,
                        lm_addr0 + (u32)(mt * 16 * SPK_STRIDE * 2) + (u32)(kt * 32));
                mma16816(d0, d1, d2, d3, a0, a1, a2, a3, bhi[kt][0], bhi[kt][1]);
                mma16816(d0, d1, d2, d3, a0, a1, a2, a3, blo[kt][0], blo[kt][1]);
            }
            const int row = mt * 16 + (lane >> 2);
            const int col = 2 * (lane & 3);
            __stcs(reinterpret_cast<float2*>(ob + (size_t)(c0 + row) * O_ + col),
                   make_float2(d0, d1));
            __stcs(reinterpret_cast<float2*>(ob + (size_t)(c0 + row + 8) * O_ + col),
                   make_float2(d2, d3));
        }
        __syncwarp();
    }
}

extern "C" void kernel_launch(void* const* d_in, const int* in_sizes, int n_in,
                              void* d_out, int out_size)
{
    const float* x  = (const float*)d_in[0];
    const float* hs = (const float*)d_in[1];
    const float* W1 = (const float*)d_in[2];
    const float* b1 = (const float*)d_in[3];
    const float* W2 = (const float*)d_in[4];
    const float* b2 = (const float*)d_in[5];

    const int B = in_sizes[1] / H_;

    float* out  = (float*)d_out;                       // (B,T,O)
    float* newh = (float*)d_out + (size_t)B * T_ * O_; // (B,T,H)

    const int blocks = (B + WPB - 1) / WPB;
    snn_kernel<<<blocks, WPB * 32>>>(x, hs, W1, b1, W2, b2, out, newh, B);
}